// round 6
// baseline (speedup 1.0000x reference)
#include <cuda_runtime.h>

// All-pairs N-body gravity — SCALAR math, 4 i-bodies per thread.
// Evidence: packed f32x2 fma is an ~3-cycle op (3 wide operands -> RF-bank
// rt=3), pinning all packed variants at ~66K cycles. Scalar FFMA sustains
// ~1/cyc/SMSP (R1 measurement) and R1 was issue-bound instead. Fix the issue
// bound: amortize the LDS.128 j-broadcast + loop overhead over 4 independent
// i-chains -> ~13.5 issue slots/pair, fma pipe (42.5K cyc/SMSP) becomes the
// binding resource.

#define BLOCK  128
#define IPT    4
#define JCHUNK 128
#define EPS2   0.0001f   // SOFTENING^2

__device__ __forceinline__ float rsq_mufu(float x) {
    float r; asm("rsqrt.approx.f32 %0, %1;" : "=f"(r) : "f"(x)); return r;
}

__global__ void zero_out_kernel(float* __restrict__ out, int n) {
    int i = blockIdx.x * blockDim.x + threadIdx.x;
    if (i < n) out[i] = 0.0f;
}

__global__ __launch_bounds__(BLOCK)
void nbody_forces_kernel(const float* __restrict__ pos,
                         const float* __restrict__ mass,
                         float* __restrict__ out) {
    __shared__ float4 sj[JCHUNK];   // {x, y, z, m}

    const int tid   = threadIdx.x;
    const int ibase = blockIdx.x * (BLOCK * IPT) + tid;
    const int jbase = blockIdx.y * JCHUNK;

    if (tid < JCHUNK) {
        int j = jbase + tid;
        sj[tid] = make_float4(pos[3 * j + 0], pos[3 * j + 1], pos[3 * j + 2],
                              mass[j]);
    }
    __syncthreads();

    float xi[IPT], yi[IPT], zi[IPT];
    float ax[IPT], ay[IPT], az[IPT];
#pragma unroll
    for (int k = 0; k < IPT; ++k) {
        int i = ibase + k * BLOCK;
        xi[k] = pos[3 * i + 0];
        yi[k] = pos[3 * i + 1];
        zi[k] = pos[3 * i + 2];
        ax[k] = 0.0f; ay[k] = 0.0f; az[k] = 0.0f;
    }

#pragma unroll 4
    for (int t = 0; t < JCHUNK; ++t) {
        const float4 p = sj[t];        // one LDS.128 broadcast feeds 4 pairs
#pragma unroll
        for (int k = 0; k < IPT; ++k) {
            float dx = p.x - xi[k];
            float dy = p.y - yi[k];
            float dz = p.z - zi[k];
            float r2 = fmaf(dx, dx, fmaf(dy, dy, fmaf(dz, dz, EPS2)));
            float inv = rsq_mufu(r2);                 // MUFU.RSQ
            float s   = (p.w * inv) * (inv * inv);    // depth 2, m * r2^-1.5
            ax[k] = fmaf(s, dx, ax[k]);
            ay[k] = fmaf(s, dy, ay[k]);
            az[k] = fmaf(s, dz, az[k]);
        }
    }

#pragma unroll
    for (int k = 0; k < IPT; ++k) {
        int i = ibase + k * BLOCK;
        atomicAdd(&out[3 * i + 0], ax[k]);
        atomicAdd(&out[3 * i + 1], ay[k]);
        atomicAdd(&out[3 * i + 2], az[k]);
    }
}

extern "C" void kernel_launch(void* const* d_in, const int* in_sizes, int n_in,
                              void* d_out, int out_size) {
    const float* pos  = (const float*)d_in[0];   // [N,3] float32
    const float* mass = (const float*)d_in[1];   // [N]   float32
    float* out = (float*)d_out;                  // [N,3] float32

    const int n = in_sizes[0] / 3;               // 8192

    zero_out_kernel<<<(out_size + 255) / 256, 256>>>(out, out_size);

    dim3 grid(n / (BLOCK * IPT), n / JCHUNK);    // 16 x 64 = 1024 CTAs
    nbody_forces_kernel<<<grid, BLOCK>>>(pos, mass, out);
}

// round 7
// speedup vs baseline: 1.0166x; 1.0166x over previous
#include <cuda_runtime.h>

// All-pairs N-body gravity — scalar math (issue-bound regime), IPT=4,
// JCHUNK=64 -> 2048 CTAs. R6 showed issue=83% at occ 30% with 16 issued
// slots/pair vs a 13-slot math floor. This round: double resident warps
// (smoother waves, higher issue efficiency) and trim per-pair overhead via
// unroll-8 + 1 LDS.128 per 4 pairs.

#define BLOCK  128
#define IPT    4
#define JCHUNK 64
#define EPS2   0.0001f   // SOFTENING^2

__device__ __forceinline__ float rsq_mufu(float x) {
    float r; asm("rsqrt.approx.f32 %0, %1;" : "=f"(r) : "f"(x)); return r;
}

__global__ void zero_out_kernel(float* __restrict__ out, int n) {
    int i = blockIdx.x * blockDim.x + threadIdx.x;
    if (i < n) out[i] = 0.0f;
}

__global__ __launch_bounds__(BLOCK)
void nbody_forces_kernel(const float* __restrict__ pos,
                         const float* __restrict__ mass,
                         float* __restrict__ out) {
    __shared__ float4 sj[JCHUNK];   // {x, y, z, m}

    const int tid   = threadIdx.x;
    const int ibase = blockIdx.x * (BLOCK * IPT) + tid;
    const int jbase = blockIdx.y * JCHUNK;

    if (tid < JCHUNK) {
        int j = jbase + tid;
        sj[tid] = make_float4(pos[3 * j + 0], pos[3 * j + 1], pos[3 * j + 2],
                              mass[j]);
    }
    __syncthreads();

    float xi[IPT], yi[IPT], zi[IPT];
    float ax[IPT], ay[IPT], az[IPT];
#pragma unroll
    for (int k = 0; k < IPT; ++k) {
        int i = ibase + k * BLOCK;
        xi[k] = pos[3 * i + 0];
        yi[k] = pos[3 * i + 1];
        zi[k] = pos[3 * i + 2];
        ax[k] = 0.0f; ay[k] = 0.0f; az[k] = 0.0f;
    }

#pragma unroll 8
    for (int t = 0; t < JCHUNK; ++t) {
        const float4 p = sj[t];        // one LDS.128 broadcast feeds 4 pairs
#pragma unroll
        for (int k = 0; k < IPT; ++k) {
            float dx = p.x - xi[k];
            float dy = p.y - yi[k];
            float dz = p.z - zi[k];
            float r2 = fmaf(dx, dx, fmaf(dy, dy, fmaf(dz, dz, EPS2)));
            float inv = rsq_mufu(r2);                 // MUFU.RSQ
            float s   = (p.w * inv) * (inv * inv);    // m * r2^-1.5, depth 2
            ax[k] = fmaf(s, dx, ax[k]);
            ay[k] = fmaf(s, dy, ay[k]);
            az[k] = fmaf(s, dz, az[k]);
        }
    }

#pragma unroll
    for (int k = 0; k < IPT; ++k) {
        int i = ibase + k * BLOCK;
        atomicAdd(&out[3 * i + 0], ax[k]);
        atomicAdd(&out[3 * i + 1], ay[k]);
        atomicAdd(&out[3 * i + 2], az[k]);
    }
}

extern "C" void kernel_launch(void* const* d_in, const int* in_sizes, int n_in,
                              void* d_out, int out_size) {
    const float* pos  = (const float*)d_in[0];   // [N,3] float32
    const float* mass = (const float*)d_in[1];   // [N]   float32
    float* out = (float*)d_out;                  // [N,3] float32

    const int n = in_sizes[0] / 3;               // 8192

    zero_out_kernel<<<(out_size + 255) / 256, 256>>>(out, out_size);

    dim3 grid(n / (BLOCK * IPT), n / JCHUNK);    // 16 x 128 = 2048 CTAs
    nbody_forces_kernel<<<grid, BLOCK>>>(pos, mass, out);
}